// round 2
// baseline (speedup 1.0000x reference)
#include <cuda_runtime.h>
#include <cuda_bf16.h>
#include <math.h>

// Problem constants
#define N_ROWS 8192
#define DIM 128
#define TILE 64
#define NTILE (N_ROWS / TILE)        // 128
#define NBLOCKS (NTILE * NTILE)      // 16384 (2D grid, lower triangle exits early)
#define PAD_ROW 68                   // 64 + 4 floats pad; 68*4=272B keeps 16B alignment

#define M_MARGIN 0.25f
#define GAMMA 256.0f
#define DELTA_P 0.75f
#define DELTA_N 0.25f

// Scratch (device globals — allocation-free per harness rules)
__device__ float g_fnorm[N_ROWS * DIM];
__device__ float g_pm[NBLOCKS];
__device__ float g_ps[NBLOCKS];
__device__ float g_nm[NBLOCKS];
__device__ float g_ns[NBLOCKS];

// ---------------------------------------------------------------------------
// online logsumexp helpers
// ---------------------------------------------------------------------------
__device__ __forceinline__ void lse_update(float& m, float& s, float l) {
    // l is always finite here
    if (l <= m) {
        s += __expf(l - m);
    } else {
        s = s * __expf(m - l) + 1.0f;   // m may be -inf: expf(-inf)=0, s=0 -> 0*0=0
        m = l;
    }
}

__device__ __forceinline__ void lse_merge(float& m, float& s, float m2, float s2) {
    float mx = fmaxf(m, m2);
    if (mx == -INFINITY) { m = mx; s = 0.0f; return; }   // both empty
    s = s * __expf(m - mx) + s2 * __expf(m2 - mx);
    m = mx;
}

// ---------------------------------------------------------------------------
// Kernel 1: L2-normalize rows. One block per row, 128 threads.
// ---------------------------------------------------------------------------
__global__ void normalize_kernel(const float* __restrict__ feats) {
    int r = blockIdx.x;
    int t = threadIdx.x;
    float v = feats[r * DIM + t];
    float sq = v * v;
    #pragma unroll
    for (int o = 16; o > 0; o >>= 1) sq += __shfl_xor_sync(0xffffffffu, sq, o);
    __shared__ float ws[4];
    if ((t & 31) == 0) ws[t >> 5] = sq;
    __syncthreads();
    float tot = ws[0] + ws[1] + ws[2] + ws[3];
    float nrm = fmaxf(sqrtf(tot), 1e-12f);
    g_fnorm[r * DIM + t] = v / nrm;
}

// ---------------------------------------------------------------------------
// Kernel 2: tiled similarity + fused masked online-logsumexp epilogue.
// Grid: (NTILE, NTILE); block 256 threads; 4x4 microtile/thread.
// Only tiles with ti <= tj do work (upper triangle).
// ---------------------------------------------------------------------------
extern __shared__ float smem_dyn[];

__global__ void __launch_bounds__(256, 3)
sim_lse_kernel(const int* __restrict__ labels) {
    const int ti = blockIdx.y;
    const int tj = blockIdx.x;
    const int bid = blockIdx.y * gridDim.x + blockIdx.x;
    const int t = threadIdx.x;

    if (ti > tj) {
        if (t == 0) {
            g_pm[bid] = -INFINITY; g_ps[bid] = 0.0f;
            g_nm[bid] = -INFINITY; g_ns[bid] = 0.0f;
        }
        return;
    }

    // smem carve-out
    float* As = smem_dyn;                         // [DIM][PAD_ROW] K-major
    float* Bs = As + DIM * PAD_ROW;               // [DIM][PAD_ROW]
    int*   lr = (int*)(Bs + DIM * PAD_ROW);       // [TILE]
    int*   lc = lr + TILE;                        // [TILE]
    float* red = (float*)(lc + TILE);             // [8*4] warp partials

    // Load feature tiles, transposed into K-major smem
    const float* arow = g_fnorm + (size_t)ti * TILE * DIM;
    const float* brow = g_fnorm + (size_t)tj * TILE * DIM;
    #pragma unroll
    for (int it = 0; it < (TILE * DIM) / 256; ++it) {
        int idx = t + it * 256;
        int r = idx >> 7;        // row within tile
        int k = idx & 127;       // dim index
        As[k * PAD_ROW + r] = arow[idx];
        Bs[k * PAD_ROW + r] = brow[idx];
    }
    if (t < TILE) {
        lr[t] = labels[ti * TILE + t];
        lc[t] = labels[tj * TILE + t];
    }
    __syncthreads();

    // 16x16 thread grid, 4x4 microtile
    const int tx = t & 15;       // row group
    const int ty = t >> 4;       // col group

    float c[4][4];
    #pragma unroll
    for (int i = 0; i < 4; ++i)
        #pragma unroll
        for (int j = 0; j < 4; ++j) c[i][j] = 0.0f;

    const float* Ab = As + tx * 4;
    const float* Bb = Bs + ty * 4;
    #pragma unroll 8
    for (int k = 0; k < DIM; ++k) {
        float4 a = *(const float4*)(Ab + k * PAD_ROW);
        float4 b = *(const float4*)(Bb + k * PAD_ROW);
        float av[4] = {a.x, a.y, a.z, a.w};
        float bv[4] = {b.x, b.y, b.z, b.w};
        #pragma unroll
        for (int i = 0; i < 4; ++i)
            #pragma unroll
            for (int j = 0; j < 4; ++j)
                c[i][j] = fmaf(av[i], bv[j], c[i][j]);
    }

    // Epilogue: mask + logits + per-thread online LSE
    float mp = -INFINITY, sp = 0.0f;
    float mn = -INFINITY, sn = 0.0f;

    const int ibase = ti * TILE + tx * 4;
    const int jbase = tj * TILE + ty * 4;
    #pragma unroll
    for (int i = 0; i < 4; ++i) {
        int gi = ibase + i;
        int li = lr[tx * 4 + i];
        #pragma unroll
        for (int j = 0; j < 4; ++j) {
            int gj = jbase + j;
            if (gi < gj) {
                float s = c[i][j];
                if (li == lc[ty * 4 + j]) {
                    float ap = fmaxf(1.0f + M_MARGIN - s, 0.0f);
                    float lp = -ap * (s - DELTA_P) * GAMMA;
                    lse_update(mp, sp, lp);
                } else {
                    float an = fmaxf(s + M_MARGIN, 0.0f);
                    float ln = an * (s - DELTA_N) * GAMMA;
                    lse_update(mn, sn, ln);
                }
            }
        }
    }

    // Warp reduction
    #pragma unroll
    for (int o = 16; o > 0; o >>= 1) {
        float m2 = __shfl_xor_sync(0xffffffffu, mp, o);
        float s2 = __shfl_xor_sync(0xffffffffu, sp, o);
        lse_merge(mp, sp, m2, s2);
        m2 = __shfl_xor_sync(0xffffffffu, mn, o);
        s2 = __shfl_xor_sync(0xffffffffu, sn, o);
        lse_merge(mn, sn, m2, s2);
    }

    __syncthreads();   // reuse smem region for reduction
    int wid = t >> 5;
    if ((t & 31) == 0) {
        red[wid * 4 + 0] = mp; red[wid * 4 + 1] = sp;
        red[wid * 4 + 2] = mn; red[wid * 4 + 3] = sn;
    }
    __syncthreads();
    if (t == 0) {
        float MP = red[0], SP = red[1], MN = red[2], SN = red[3];
        #pragma unroll
        for (int w = 1; w < 8; ++w) {
            lse_merge(MP, SP, red[w * 4 + 0], red[w * 4 + 1]);
            lse_merge(MN, SN, red[w * 4 + 2], red[w * 4 + 3]);
        }
        g_pm[bid] = MP; g_ps[bid] = SP;
        g_nm[bid] = MN; g_ns[bid] = SN;
    }
}

// ---------------------------------------------------------------------------
// Kernel 3: final reduction across all block partials + softplus
// ---------------------------------------------------------------------------
__global__ void final_kernel(float* __restrict__ out) {
    int t = threadIdx.x;
    float mp = -INFINITY, sp = 0.0f;
    float mn = -INFINITY, sn = 0.0f;
    for (int i = t; i < NBLOCKS; i += 256) {
        lse_merge(mp, sp, g_pm[i], g_ps[i]);
        lse_merge(mn, sn, g_nm[i], g_ns[i]);
    }
    #pragma unroll
    for (int o = 16; o > 0; o >>= 1) {
        float m2 = __shfl_xor_sync(0xffffffffu, mp, o);
        float s2 = __shfl_xor_sync(0xffffffffu, sp, o);
        lse_merge(mp, sp, m2, s2);
        m2 = __shfl_xor_sync(0xffffffffu, mn, o);
        s2 = __shfl_xor_sync(0xffffffffu, sn, o);
        lse_merge(mn, sn, m2, s2);
    }
    __shared__ float red[8 * 4];
    int wid = t >> 5;
    if ((t & 31) == 0) {
        red[wid * 4 + 0] = mp; red[wid * 4 + 1] = sp;
        red[wid * 4 + 2] = mn; red[wid * 4 + 3] = sn;
    }
    __syncthreads();
    if (t == 0) {
        float MP = red[0], SP = red[1], MN = red[2], SN = red[3];
        #pragma unroll
        for (int w = 1; w < 8; ++w) {
            lse_merge(MP, SP, red[w * 4 + 0], red[w * 4 + 1]);
            lse_merge(MN, SN, red[w * 4 + 2], red[w * 4 + 3]);
        }
        float lse_p = MP + logf(SP);
        float lse_n = MN + logf(SN);
        float x = lse_p + lse_n;
        // softplus, numerically stable
        out[0] = fmaxf(x, 0.0f) + log1pf(__expf(-fabsf(x)));
    }
}

// ---------------------------------------------------------------------------
extern "C" void kernel_launch(void* const* d_in, const int* in_sizes, int n_in,
                              void* d_out, int out_size) {
    const float* feats = (const float*)d_in[0];
    const int* labels = (const int*)d_in[1];
    float* out = (float*)d_out;

    // dynamic smem for sim kernel: 2 tiles + labels + reduction scratch
    const int smem_bytes = (2 * DIM * PAD_ROW) * (int)sizeof(float)
                         + 2 * TILE * (int)sizeof(int)
                         + 8 * 4 * (int)sizeof(float);
    cudaFuncSetAttribute(sim_lse_kernel,
                         cudaFuncAttributeMaxDynamicSharedMemorySize, smem_bytes);

    normalize_kernel<<<N_ROWS, DIM>>>(feats);

    dim3 grid(NTILE, NTILE);
    sim_lse_kernel<<<grid, 256, smem_bytes>>>(labels);

    final_kernel<<<1, 256>>>(out);
}

// round 3
// speedup vs baseline: 1.1519x; 1.1519x over previous
#include <cuda_runtime.h>
#include <cuda_bf16.h>
#include <math.h>
#include <stdint.h>

// Problem constants
#define N_ROWS 8192
#define DIM 128
#define TILE 64
#define NTILE (N_ROWS / TILE)                 // 128
#define NB_TRI (NTILE * (NTILE + 1) / 2)      // 8256 upper-tri tiles
#define PAD_ROW 68                            // 64 + 4 floats pad

#define M_MARGIN 0.25f
#define GAMMA 256.0f
#define DELTA_P 0.75f
#define DELTA_N 0.25f

// Scratch (device globals — allocation-free per harness rules)
__device__ float g_fnorm[N_ROWS * DIM];
__device__ float g_pm[NB_TRI];
__device__ float g_ps[NB_TRI];
__device__ float g_nm[NB_TRI];
__device__ float g_ns[NB_TRI];

// ---------------------------------------------------------------------------
// packed f32x2 helpers (sm_103a FFMA2 — ptxas never auto-emits; PTX only)
// ---------------------------------------------------------------------------
__device__ __forceinline__ uint64_t pack_dup(float x) {
    uint64_t r;
    asm("mov.b64 %0, {%1, %1};" : "=l"(r) : "f"(x));
    return r;
}
__device__ __forceinline__ void ffma2(uint64_t& d, uint64_t a, uint64_t b) {
    asm("fma.rn.f32x2 %0, %1, %2, %0;" : "+l"(d) : "l"(a), "l"(b));
}
__device__ __forceinline__ float2 unpack2(uint64_t v) {
    float2 r;
    asm("mov.b64 {%0, %1}, %2;" : "=f"(r.x), "=f"(r.y) : "l"(v));
    return r;
}

// ---------------------------------------------------------------------------
// online logsumexp helpers
// ---------------------------------------------------------------------------
__device__ __forceinline__ void lse_update(float& m, float& s, float l) {
    if (l <= m) {
        s += __expf(l - m);
    } else {
        s = s * __expf(m - l) + 1.0f;
        m = l;
    }
}

__device__ __forceinline__ void lse_merge(float& m, float& s, float m2, float s2) {
    float mx = fmaxf(m, m2);
    if (mx == -INFINITY) { m = mx; s = 0.0f; return; }
    s = s * __expf(m - mx) + s2 * __expf(m2 - mx);
    m = mx;
}

// ---------------------------------------------------------------------------
// Kernel 1: L2-normalize rows. One block per row, 128 threads.
// ---------------------------------------------------------------------------
__global__ void normalize_kernel(const float* __restrict__ feats) {
    int r = blockIdx.x;
    int t = threadIdx.x;
    float v = feats[r * DIM + t];
    float sq = v * v;
    #pragma unroll
    for (int o = 16; o > 0; o >>= 1) sq += __shfl_xor_sync(0xffffffffu, sq, o);
    __shared__ float ws[4];
    if ((t & 31) == 0) ws[t >> 5] = sq;
    __syncthreads();
    float tot = ws[0] + ws[1] + ws[2] + ws[3];
    float nrm = fmaxf(sqrtf(tot), 1e-12f);
    g_fnorm[r * DIM + t] = v / nrm;
}

// ---------------------------------------------------------------------------
// Triangular linear-index -> (ti, tj), ti <= tj
// offset(ti) = ti*NTILE - ti*(ti-1)/2
// ---------------------------------------------------------------------------
__device__ __forceinline__ int tri_offset(int ti) {
    return ti * NTILE - (ti * (ti - 1)) / 2;
}

// ---------------------------------------------------------------------------
// Kernel 2: tiled similarity + fused masked online-logsumexp epilogue.
// Grid: NB_TRI linear; block 256 threads; 4x4 microtile with packed f32x2 FMA.
// ---------------------------------------------------------------------------
extern __shared__ float smem_dyn[];

__global__ void __launch_bounds__(256, 3)
sim_lse_kernel(const int* __restrict__ labels) {
    const int bid = blockIdx.x;
    const int t = threadIdx.x;

    // invert triangular index
    int L = bid;
    float disc = (float)((2 * NTILE + 1) * (2 * NTILE + 1)) - 8.0f * (float)L;
    int ti = (int)(((float)(2 * NTILE + 1) - sqrtf(disc)) * 0.5f);
    if (ti < 0) ti = 0;
    if (ti > NTILE - 1) ti = NTILE - 1;
    while (ti + 1 <= NTILE - 1 && tri_offset(ti + 1) <= L) ++ti;
    while (tri_offset(ti) > L) --ti;
    const int tj = ti + (L - tri_offset(ti));

    // smem carve-out
    float* As = smem_dyn;                         // [DIM][PAD_ROW] K-major
    float* Bs = As + DIM * PAD_ROW;               // [DIM][PAD_ROW]
    int*   lr = (int*)(Bs + DIM * PAD_ROW);       // [TILE]
    int*   lc = lr + TILE;                        // [TILE]
    float* red = (float*)(lc + TILE);             // [8*4] warp partials

    // Load feature tiles, transposed into K-major smem
    const float* arow = g_fnorm + (size_t)ti * TILE * DIM;
    const float* brow = g_fnorm + (size_t)tj * TILE * DIM;
    #pragma unroll
    for (int it = 0; it < (TILE * DIM) / 256; ++it) {
        int idx = t + it * 256;
        int r = idx >> 7;        // row within tile
        int k = idx & 127;       // dim index
        As[k * PAD_ROW + r] = arow[idx];
        Bs[k * PAD_ROW + r] = brow[idx];
    }
    if (t < TILE) {
        lr[t] = labels[ti * TILE + t];
        lc[t] = labels[tj * TILE + t];
    }
    __syncthreads();

    // 16x16 thread grid, 4x4 microtile; accumulators packed pairwise along j
    const int tx = t & 15;       // row group
    const int ty = t >> 4;       // col group

    uint64_t c2[4][2];
    #pragma unroll
    for (int i = 0; i < 4; ++i) {
        c2[i][0] = 0ull;         // two packed +0.0f
        c2[i][1] = 0ull;
    }

    const float* Ab = As + tx * 4;
    const float* Bb = Bs + ty * 4;
    #pragma unroll 16
    for (int k = 0; k < DIM; ++k) {
        float4 a = *(const float4*)(Ab + k * PAD_ROW);
        ulonglong2 b = *(const ulonglong2*)(Bb + k * PAD_ROW);
        uint64_t a0 = pack_dup(a.x);
        uint64_t a1 = pack_dup(a.y);
        uint64_t a2 = pack_dup(a.z);
        uint64_t a3 = pack_dup(a.w);
        ffma2(c2[0][0], a0, b.x);  ffma2(c2[0][1], a0, b.y);
        ffma2(c2[1][0], a1, b.x);  ffma2(c2[1][1], a1, b.y);
        ffma2(c2[2][0], a2, b.x);  ffma2(c2[2][1], a2, b.y);
        ffma2(c2[3][0], a3, b.x);  ffma2(c2[3][1], a3, b.y);
    }

    // Epilogue: unpack, mask + logits + per-thread online LSE
    float mp = -INFINITY, sp = 0.0f;
    float mn = -INFINITY, sn = 0.0f;

    const int ibase = ti * TILE + tx * 4;
    const int jbase = tj * TILE + ty * 4;
    #pragma unroll
    for (int i = 0; i < 4; ++i) {
        int gi = ibase + i;
        int li = lr[tx * 4 + i];
        float cv[4];
        float2 p0 = unpack2(c2[i][0]);
        float2 p1 = unpack2(c2[i][1]);
        cv[0] = p0.x; cv[1] = p0.y; cv[2] = p1.x; cv[3] = p1.y;
        #pragma unroll
        for (int j = 0; j < 4; ++j) {
            int gj = jbase + j;
            if (gi < gj) {
                float s = cv[j];
                if (li == lc[ty * 4 + j]) {
                    float ap = fmaxf(1.0f + M_MARGIN - s, 0.0f);
                    float lp = -ap * (s - DELTA_P) * GAMMA;
                    lse_update(mp, sp, lp);
                } else {
                    float an = fmaxf(s + M_MARGIN, 0.0f);
                    float ln = an * (s - DELTA_N) * GAMMA;
                    lse_update(mn, sn, ln);
                }
            }
        }
    }

    // Warp reduction
    #pragma unroll
    for (int o = 16; o > 0; o >>= 1) {
        float m2 = __shfl_xor_sync(0xffffffffu, mp, o);
        float s2 = __shfl_xor_sync(0xffffffffu, sp, o);
        lse_merge(mp, sp, m2, s2);
        m2 = __shfl_xor_sync(0xffffffffu, mn, o);
        s2 = __shfl_xor_sync(0xffffffffu, sn, o);
        lse_merge(mn, sn, m2, s2);
    }

    __syncthreads();   // smem reuse for reduction
    int wid = t >> 5;
    if ((t & 31) == 0) {
        red[wid * 4 + 0] = mp; red[wid * 4 + 1] = sp;
        red[wid * 4 + 2] = mn; red[wid * 4 + 3] = sn;
    }
    __syncthreads();
    if (t == 0) {
        float MP = red[0], SP = red[1], MN = red[2], SN = red[3];
        #pragma unroll
        for (int w = 1; w < 8; ++w) {
            lse_merge(MP, SP, red[w * 4 + 0], red[w * 4 + 1]);
            lse_merge(MN, SN, red[w * 4 + 2], red[w * 4 + 3]);
        }
        g_pm[bid] = MP; g_ps[bid] = SP;
        g_nm[bid] = MN; g_ns[bid] = SN;
    }
}

// ---------------------------------------------------------------------------
// Kernel 3: final reduction across all block partials + softplus
// ---------------------------------------------------------------------------
__global__ void final_kernel(float* __restrict__ out) {
    int t = threadIdx.x;
    float mp = -INFINITY, sp = 0.0f;
    float mn = -INFINITY, sn = 0.0f;
    for (int i = t; i < NB_TRI; i += 256) {
        lse_merge(mp, sp, g_pm[i], g_ps[i]);
        lse_merge(mn, sn, g_nm[i], g_ns[i]);
    }
    #pragma unroll
    for (int o = 16; o > 0; o >>= 1) {
        float m2 = __shfl_xor_sync(0xffffffffu, mp, o);
        float s2 = __shfl_xor_sync(0xffffffffu, sp, o);
        lse_merge(mp, sp, m2, s2);
        m2 = __shfl_xor_sync(0xffffffffu, mn, o);
        s2 = __shfl_xor_sync(0xffffffffu, sn, o);
        lse_merge(mn, sn, m2, s2);
    }
    __shared__ float red[8 * 4];
    int wid = t >> 5;
    if ((t & 31) == 0) {
        red[wid * 4 + 0] = mp; red[wid * 4 + 1] = sp;
        red[wid * 4 + 2] = mn; red[wid * 4 + 3] = sn;
    }
    __syncthreads();
    if (t == 0) {
        float MP = red[0], SP = red[1], MN = red[2], SN = red[3];
        #pragma unroll
        for (int w = 1; w < 8; ++w) {
            lse_merge(MP, SP, red[w * 4 + 0], red[w * 4 + 1]);
            lse_merge(MN, SN, red[w * 4 + 2], red[w * 4 + 3]);
        }
        float lse_p = MP + logf(SP);
        float lse_n = MN + logf(SN);
        float x = lse_p + lse_n;
        out[0] = fmaxf(x, 0.0f) + log1pf(__expf(-fabsf(x)));
    }
}

// ---------------------------------------------------------------------------
extern "C" void kernel_launch(void* const* d_in, const int* in_sizes, int n_in,
                              void* d_out, int out_size) {
    const float* feats = (const float*)d_in[0];
    const int* labels = (const int*)d_in[1];
    float* out = (float*)d_out;

    const int smem_bytes = (2 * DIM * PAD_ROW) * (int)sizeof(float)
                         + 2 * TILE * (int)sizeof(int)
                         + 8 * 4 * (int)sizeof(float);
    cudaFuncSetAttribute(sim_lse_kernel,
                         cudaFuncAttributeMaxDynamicSharedMemorySize, smem_bytes);

    normalize_kernel<<<N_ROWS, DIM>>>(feats);
    sim_lse_kernel<<<NB_TRI, 256, smem_bytes>>>(labels);
    final_kernel<<<1, 256>>>(out);
}